// round 1
// baseline (speedup 1.0000x reference)
#include <cuda_runtime.h>
#include <math.h>

// Problem constants (fixed by the dataset)
#define NMAXN 50000
#define EMAXE 1600000
#define LDA   4160          // mom row stride: 64*64 conv moments + 64 dense-branch cols

struct __align__(16) EdgeRec { int j; int kp; float fu; float fv; };

// ---------------- scratch (static device globals; no allocations) ----------------
__device__ int      g_deg[NMAXN];
__device__ int      g_cur[NMAXN];
__device__ int      g_off[NMAXN + 1];
__device__ EdgeRec  g_recs[EMAXE];
__device__ float    g_mom[(size_t)NMAXN * LDA];   // ~832 MB scratch
__device__ float    g_ansA[(size_t)NMAXN * 64];
__device__ float    g_ansB[(size_t)NMAXN * 64];
__device__ float    g_W[LDA * 64];
__device__ float    g_bias[64];

// ---------------- CSR build ----------------
__global__ void k_zero(int n) {
    int i = blockIdx.x * blockDim.x + threadIdx.x;
    if (i < n) { g_deg[i] = 0; g_cur[i] = 0; }
}

__global__ void k_hist(const int* __restrict__ ei, int E) {
    int e = blockIdx.x * blockDim.x + threadIdx.x;
    if (e < E) atomicAdd(&g_deg[ei[e]], 1);
}

__global__ void k_scan(int n) {
    __shared__ int buf[1024];
    __shared__ int carry;
    int t = threadIdx.x;
    if (t == 0) carry = 0;
    __syncthreads();
    for (int base = 0; base < n; base += 1024) {
        int v = (base + t < n) ? g_deg[base + t] : 0;
        buf[t] = v;
        __syncthreads();
        for (int o = 1; o < 1024; o <<= 1) {
            int add = (t >= o) ? buf[t - o] : 0;
            __syncthreads();
            buf[t] += add;
            __syncthreads();
        }
        int excl = ((t > 0) ? buf[t - 1] : 0) + carry;
        if (base + t < n) g_off[base + t] = excl;
        __syncthreads();
        if (t == 0) carry += buf[1023];
        __syncthreads();
    }
    if (t == 0) g_off[n] = carry;
}

// Scatter edges into CSR order; precompute 4-sparse hat-basis record per edge.
__global__ void k_scatter(const float* __restrict__ P,
                          const int* __restrict__ ei, const int* __restrict__ ej, int E) {
    int e = blockIdx.x * blockDim.x + threadIdx.x;
    if (e >= E) return;
    int i = ei[e], j = ej[e];
    int pos = g_off[i] + atomicAdd(&g_cur[i], 1);

    float dx = P[2 * i]     - P[2 * j];
    float dy = P[2 * i + 1] - P[2 * j + 1];
    dx = fminf(fmaxf(dx, -1.f), 1.f);
    dy = fminf(fmaxf(dy, -1.f), 1.f);
    int valid = (i != j) ? 1 : 0;

    float r = sqrtf(dx * dx + dy * dy + 1e-12f);
    float u = fminf(fmaxf(2.f * r - 1.f, -1.f), 1.f);
    float v = atan2f(dy, dx) * 0.3183098861837907f;   // 1/pi

    float pu = (u + 1.f) * 3.5f;           // 8 centers -> spacing 2/7
    int   iu = min(6, (int)pu);
    float fu = pu - (float)iu;
    float pv = (v + 1.f) * 3.5f;
    int   iv = min(6, (int)pv);
    float fv = pv - (float)iv;

    EdgeRec r2;
    r2.j  = j;
    r2.kp = iu | (iv << 8) | (valid << 16);
    r2.fu = fu;
    r2.fv = fv;
    g_recs[pos] = r2;
}

// ---------------- moment kernel ----------------
// One 64-thread block per node. smem cell idx is owned by thread (idx % 64):
// no atomics, no barriers in the accumulation loop.
template<int CIN, bool RELU>
__global__ void k_moment(const float* __restrict__ xext, int xsel, int n) {
    int node = blockIdx.x;
    if (node >= n) return;
    int t = threadIdx.x;  // 64 threads
    const float* x = (xsel == 0) ? g_ansA : (xsel == 1) ? g_ansB : xext;

    __shared__ float sm[CIN * 64];
#pragma unroll
    for (int ii = t; ii < CIN * 64; ii += 64) sm[ii] = 0.f;

    int s = g_off[node], e = g_off[node + 1];
    for (int p = s; p < e; p++) {
        EdgeRec r = g_recs[p];
        if (!((r.kp >> 16) & 1)) continue;  // self edge -> basis masked to 0
        float xv = 0.f;
        float4 x4 = make_float4(0.f, 0.f, 0.f, 0.f);
        if (CIN == 64) {
            xv = x[(size_t)r.j * 64 + t];
            if (RELU) xv = fmaxf(xv, 0.f);
        } else {
            x4 = *(const float4*)(x + (size_t)r.j * 4);
        }
        int   iu = r.kp & 255, iv = (r.kp >> 8) & 255;
        float fu = r.fu, fv = r.fv;
        float wu0 = 1.f - fu, wu1 = fu, wv0 = 1.f - fv, wv1 = fv;
        int k00 = iu * 8 + iv;
#pragma unroll
        for (int q = 0; q < 4; q++) {
            int   k = k00 + ((q >> 1) ? 8 : 0) + (q & 1);
            float w = ((q >> 1) ? wu1 : wu0) * ((q & 1) ? wv1 : wv0);
            if (CIN == 64) {
                sm[k * 64 + t] += w * xv;
            } else {
                int c = t - ((k * CIN) & 63);
                if ((unsigned)c < (unsigned)CIN) {
                    float xc = (c == 0) ? x4.x : (c == 1) ? x4.y : (c == 2) ? x4.z : x4.w;
                    sm[k * CIN + c] += w * xc;
                }
            }
        }
    }

    float* row = g_mom + (size_t)node * LDA;
#pragma unroll
    for (int ii = t; ii < CIN * 64; ii += 64) row[ii] = sm[ii];

    // dense-branch chunk appended to the mom row
    if (CIN == 64) {
        float a = x[(size_t)node * 64 + t];
        if (RELU) a = fmaxf(a, 0.f);
        row[4096 + t] = a;
    } else {
        if (t < 16) row[256 + t] = (t < 4) ? xext[(size_t)node * 4 + t] : 0.f;
    }
}

// ---------------- weight packing ----------------
// Layer 0: out = [ff@fw0 | conv0].  W0 is [272 x 64]; rows 0..255 = cw0 into cols 32..63,
// rows 256..259 = fw0 into cols 0..31, rows 260..271 zero pad.
__global__ void k_pack0(const float* __restrict__ cw0, const float* __restrict__ fw0,
                        const float* __restrict__ cb0, const float* __restrict__ fb0) {
    int idx = blockIdx.x * blockDim.x + threadIdx.x;
    if (idx < 272 * 64) {
        int r = idx / 64, co = idx % 64;
        float v = 0.f;
        if (r < 256) {
            if (co >= 32) v = cw0[r * 32 + (co - 32)];
        } else if (r < 260) {
            int c = r - 256;
            if (co < 32) v = fw0[c * 32 + co];
        }
        g_W[idx] = v;
    }
    if (idx < 64) g_bias[idx] = (idx < 32) ? fb0[idx] : cb0[idx - 32];
}

// Layers 1..3: W = [cw flat (4096 x Cout); fw (64 x Cout)], bias = cb + fb.
__global__ void k_pack(const float* __restrict__ cw, const float* __restrict__ fw,
                       const float* __restrict__ cb, const float* __restrict__ fb, int cout) {
    int idx = blockIdx.x * blockDim.x + threadIdx.x;
    int convN = 4096 * cout, tot = LDA * cout;
    if (idx < convN)      g_W[idx] = cw[idx];
    else if (idx < tot)   g_W[idx] = fw[idx - convN];
    if (idx < cout)       g_bias[idx] = cb[idx] + fb[idx];
}

// ---------------- fp32 SGEMM: C[64 x 64] per block, 256 threads, 4x4 microtile ----------------
__global__ void k_sgemm64(int KD, int n, int outSel, int residSel) {
    __shared__ float As[16][68];
    __shared__ float Bs[16][64];
    float*       out   = (outSel == 0) ? g_ansA : g_ansB;
    const float* resid = (residSel == 0) ? g_ansA : (residSel == 1) ? g_ansB : nullptr;

    int tid  = threadIdx.x;                 // 256
    int row0 = blockIdx.x * 64;
    int tx = tid & 15, ty = tid >> 4;       // C[ty*4+i][tx*4+j]
    int am = tid >> 2, ak = (tid & 3) << 2; // A loader: row am, 4 consecutive k
    int bk = tid >> 4, bn = (tid & 15) << 2;

    float acc[4][4];
#pragma unroll
    for (int i = 0; i < 4; i++)
#pragma unroll
        for (int j = 0; j < 4; j++) acc[i][j] = 0.f;

    for (int k0 = 0; k0 < KD; k0 += 16) {
        float4 av = make_float4(0.f, 0.f, 0.f, 0.f);
        int gm = row0 + am;
        if (gm < n) av = *(const float4*)(g_mom + (size_t)gm * LDA + k0 + ak);
        float4 bv = *(const float4*)(g_W + (size_t)(k0 + bk) * 64 + bn);
        __syncthreads();
        As[ak + 0][am] = av.x; As[ak + 1][am] = av.y;
        As[ak + 2][am] = av.z; As[ak + 3][am] = av.w;
        *(float4*)&Bs[bk][bn] = bv;
        __syncthreads();
#pragma unroll
        for (int kk = 0; kk < 16; kk++) {
            float4 a4 = *(const float4*)&As[kk][ty * 4];
            float4 b4 = *(const float4*)&Bs[kk][tx * 4];
            acc[0][0] = fmaf(a4.x, b4.x, acc[0][0]); acc[0][1] = fmaf(a4.x, b4.y, acc[0][1]);
            acc[0][2] = fmaf(a4.x, b4.z, acc[0][2]); acc[0][3] = fmaf(a4.x, b4.w, acc[0][3]);
            acc[1][0] = fmaf(a4.y, b4.x, acc[1][0]); acc[1][1] = fmaf(a4.y, b4.y, acc[1][1]);
            acc[1][2] = fmaf(a4.y, b4.z, acc[1][2]); acc[1][3] = fmaf(a4.y, b4.w, acc[1][3]);
            acc[2][0] = fmaf(a4.z, b4.x, acc[2][0]); acc[2][1] = fmaf(a4.z, b4.y, acc[2][1]);
            acc[2][2] = fmaf(a4.z, b4.z, acc[2][2]); acc[2][3] = fmaf(a4.z, b4.w, acc[2][3]);
            acc[3][0] = fmaf(a4.w, b4.x, acc[3][0]); acc[3][1] = fmaf(a4.w, b4.y, acc[3][1]);
            acc[3][2] = fmaf(a4.w, b4.z, acc[3][2]); acc[3][3] = fmaf(a4.w, b4.w, acc[3][3]);
        }
    }

#pragma unroll
    for (int i = 0; i < 4; i++) {
        int m = row0 + ty * 4 + i;
        if (m >= n) continue;
#pragma unroll
        for (int j = 0; j < 4; j++) {
            int nn = tx * 4 + j;
            float v = acc[i][j] + g_bias[nn];
            if (resid) v += resid[(size_t)m * 64 + nn];
            out[(size_t)m * 64 + nn] = v;
        }
    }
}

// ---------------- layer 3: [N,4160] x [4160,2], warp per node, /128 epilogue ----------------
__global__ void k_gemv2(float* __restrict__ out, int n) {
    __shared__ float w0[LDA];
    __shared__ float w1[LDA];
    int tid = threadIdx.x;  // 256
    for (int i = tid; i < LDA; i += 256) { w0[i] = g_W[2 * i]; w1[i] = g_W[2 * i + 1]; }
    __syncthreads();
    int warp = tid >> 5, lane = tid & 31;
    int node = blockIdx.x * 8 + warp;
    if (node >= n) return;
    const float* a = g_mom + (size_t)node * LDA;
    float s0 = 0.f, s1 = 0.f;
    for (int v = lane; v < LDA; v += 32) {
        float av = a[v];
        s0 = fmaf(av, w0[v], s0);
        s1 = fmaf(av, w1[v], s1);
    }
#pragma unroll
    for (int o = 16; o > 0; o >>= 1) {
        s0 += __shfl_down_sync(0xffffffffu, s0, o);
        s1 += __shfl_down_sync(0xffffffffu, s1, o);
    }
    if (lane == 0) {
        out[(size_t)node * 2]     = (s0 + g_bias[0]) * (1.f / 128.f);
        out[(size_t)node * 2 + 1] = (s1 + g_bias[1]) * (1.f / 128.f);
    }
}

// ---------------- launch ----------------
extern "C" void kernel_launch(void* const* d_in, const int* in_sizes, int n_in,
                              void* d_out, int out_size) {
    const float* P   = (const float*)d_in[0];
    const float* FF  = (const float*)d_in[1];
    const int*   EI  = (const int*)d_in[2];
    const int*   EJ  = (const int*)d_in[3];
    const float* cw0 = (const float*)d_in[4],  *cb0 = (const float*)d_in[5];
    const float* fw0 = (const float*)d_in[6],  *fb0 = (const float*)d_in[7];
    const float* cw1 = (const float*)d_in[8],  *cb1 = (const float*)d_in[9];
    const float* fw1 = (const float*)d_in[10], *fb1 = (const float*)d_in[11];
    const float* cw2 = (const float*)d_in[12], *cb2 = (const float*)d_in[13];
    const float* fw2 = (const float*)d_in[14], *fb2 = (const float*)d_in[15];
    const float* cw3 = (const float*)d_in[16], *cb3 = (const float*)d_in[17];
    const float* fw3 = (const float*)d_in[18], *fb3 = (const float*)d_in[19];

    int N = in_sizes[0] / 2;
    int E = in_sizes[2];
    float* OUT = (float*)d_out;

    // CSR + basis
    k_zero<<<(N + 255) / 256, 256>>>(N);
    k_hist<<<(E + 255) / 256, 256>>>(EI, E);
    k_scan<<<1, 1024>>>(N);
    k_scatter<<<(E + 255) / 256, 256>>>(P, EI, EJ, E);

    int gW = (LDA * 64 + 255) / 256;
    int gG = (N + 63) / 64;

    // layer 0: ans(A) = [ff@fw0 | conv0(ff)]
    k_pack0<<<(272 * 64 + 255) / 256, 256>>>(cw0, fw0, cb0, fb0);
    k_moment<4, false><<<N, 64>>>(FF, -1, N);
    k_sgemm64<<<gG, 256>>>(272, N, /*out=A*/0, /*resid*/-1);

    // layer 1: ans(B) = conv(relu(A)) + relu(A)@fw1 + b1
    k_pack<<<gW, 256>>>(cw1, fw1, cb1, fb1, 64);
    k_moment<64, true><<<N, 64>>>(nullptr, 0, N);
    k_sgemm64<<<gG, 256>>>(LDA, N, /*out=B*/1, /*resid*/-1);

    // layer 2: ans(A) = conv(relu(B)) + relu(B)@fw2 + b2 + B
    k_pack<<<gW, 256>>>(cw2, fw2, cb2, fb2, 64);
    k_moment<64, true><<<N, 64>>>(nullptr, 1, N);
    k_sgemm64<<<gG, 256>>>(LDA, N, /*out=A*/0, /*resid=B*/1);

    // layer 3: out = (conv(relu(A)) + relu(A)@fw3 + b3) / 128
    k_pack<<<gW, 256>>>(cw3, fw3, cb3, fb3, 2);
    k_moment<64, true><<<N, 64>>>(nullptr, 0, N);
    k_gemv2<<<(N + 7) / 8, 256>>>(OUT, N);
}